// round 14
// baseline (speedup 1.0000x reference)
#include <cuda_runtime.h>
#include <cuda_bf16.h>
#include <math.h>
#include <stdint.h>

#define NA 100
#define DM 256
#define HID 256
#define BATCH 64
#define NPAIR 4950
#define PT 64           // pairs per CTA tile
#define PTILES 78       // ceil(4950/64)
#define VTILES 7        // vols row-groups of 16

// ---------------- device scratch (no allocation allowed) ----------------
__device__ float g_R[BATCH * NA * NA];
__device__ float g_vols[BATCH * NA];
__device__ __nv_bfloat16 g_w1t_hi[HID * DM];  // [n][k] K-major
__device__ __nv_bfloat16 g_w1t_lo[HID * DM];

__device__ __forceinline__ uint32_t smem_u32(const void* p) {
  uint32_t a;
  asm("{ .reg .u64 t; cvta.to.shared.u64 t, %1; cvt.u32.u64 %0, t; }"
      : "=r"(a) : "l"(p));
  return a;
}
__device__ __forceinline__ void ldsm_x4(uint32_t (&r)[4], uint32_t addr) {
  asm volatile(
      "ldmatrix.sync.aligned.m8n8.x4.shared.b16 {%0,%1,%2,%3}, [%4];"
      : "=r"(r[0]), "=r"(r[1]), "=r"(r[2]), "=r"(r[3]) : "r"(addr));
}
__device__ __forceinline__ void ldsm_x2(uint32_t (&r)[2], uint32_t addr) {
  asm volatile(
      "ldmatrix.sync.aligned.m8n8.x2.shared.b16 {%0,%1}, [%2];"
      : "=r"(r[0]), "=r"(r[1]) : "r"(addr));
}
__device__ __forceinline__ void mma16816(float (&d)[4], const uint32_t (&a)[4],
                                         const uint32_t (&b)[2]) {
  asm volatile(
      "mma.sync.aligned.m16n8k16.row.col.f32.bf16.bf16.f32 "
      "{%0,%1,%2,%3}, {%4,%5,%6,%7}, {%8,%9}, {%0,%1,%2,%3};"
      : "+f"(d[0]), "+f"(d[1]), "+f"(d[2]), "+f"(d[3])
      : "r"(a[0]), "r"(a[1]), "r"(a[2]), "r"(a[3]), "r"(b[0]), "r"(b[1]));
}
__device__ __forceinline__ uint32_t pack_bf16(float a, float b) {
  __nv_bfloat16 h0 = __float2bfloat16(a), h1 = __float2bfloat16(b);
  return ((uint32_t)*(uint16_t*)&h1 << 16) | *(uint16_t*)&h0;
}

// ---------------------------------------------------------------------------
__global__ void prep_w1t(const float* __restrict__ w1) {
  int n = blockIdx.x, k = threadIdx.x;
  float v = w1[k * HID + n];
  __nv_bfloat16 h = __float2bfloat16(v);
  float r = v - __bfloat162float(h);
  g_w1t_hi[n * DM + k] = h;
  g_w1t_lo[n * DM + k] = __float2bfloat16(r);
}

// ---------------------------------------------------------------------------
// FUSED pair MLP (tiles 0..77) + vols MLP (tiles 78..84), per batch.
// pair: mma.sync bf16 2-way split, 3 passes, DOUBLE-BUFFERED smem pipeline,
// 2 CTAs/SM (207 KB smem total, <=128 regs).
// ---------------------------------------------------------------------------
#define SBUF 51200     // bytes per stage
#define SO_A_HI 0
#define SO_A_LO 5120
#define SO_B_HI 10240
#define SO_B_LO 30720
#define OFF_SI  102400
#define OFF_SJ  102656
#define OFF_B1  102912
#define OFF_W2  103936
#define OFF_RED 104960
#define SMEM_PAIR 105984

__global__ __launch_bounds__(256, 2) void pair_mma_kernel(
    const float* __restrict__ x,
    const float* __restrict__ vw1, const float* __restrict__ vb1,
    const float* __restrict__ vw2, const float* __restrict__ vb2,
    const float* __restrict__ b1, const float* __restrict__ w2,
    const float* __restrict__ b2) {
  extern __shared__ char smem[];
  uint32_t sb = smem_u32(smem);
  int b = blockIdx.y, tile = blockIdx.x;
  int tid = threadIdx.x, lane = tid & 31, warp = tid >> 5;
  const float* emb = x + ((size_t)b * 64 + 63) * NA * DM;

  if (tile >= PTILES) {
    // ================= vols branch =================
    int r0 = (tile - PTILES) * 16;
    float* es = (float*)smem;                  // [16][256]
    float* red = (float*)(smem + 16 * DM * 4); // [16][8]

    for (int idx = tid; idx < 16 * DM; idx += 256) {
      int r = idx >> 8, d = idx & 255;
      es[r * DM + d] = (r0 + r < NA) ? emb[(r0 + r) * DM + d] : 0.f;
    }
    __syncthreads();

    float acc[16];
    float bb = vb1[tid];
#pragma unroll
    for (int r = 0; r < 16; r++) acc[r] = bb;

#pragma unroll 4
    for (int d = 0; d < DM; d++) {
      float w = vw1[d * HID + tid];
#pragma unroll
      for (int r = 0; r < 16; r++) acc[r] = fmaf(es[r * DM + d], w, acc[r]);
    }

    float wv = vw2[tid];
#pragma unroll
    for (int r = 0; r < 16; r++) {
      float v = fmaxf(acc[r], 0.f) * wv;
#pragma unroll
      for (int o = 16; o; o >>= 1) v += __shfl_xor_sync(0xffffffffu, v, o);
      if (lane == 0) red[r * 8 + warp] = v;
    }
    __syncthreads();
    if (tid < 16) {
      float s = 0.f;
#pragma unroll
      for (int w = 0; w < 8; w++) s += red[tid * 8 + w];
      s += vb2[0];
      float sp = fmaxf(s, 0.f) + log1pf(expf(-fabsf(s)));
      if (r0 + tid < NA) g_vols[b * NA + r0 + tid] = sp + 1e-6f;
    }
    return;
  }

  // ================= pair branch =================
  int wm = warp >> 2, wn = warp & 3;   // 2 x 4 warps

  int* si = (int*)(smem + OFF_SI);
  int* sj = (int*)(smem + OFF_SJ);
  float* b1s = (float*)(smem + OFF_B1);
  float* w2s = (float*)(smem + OFF_W2);
  float* red = (float*)(smem + OFF_RED);

  if (tid < PT) {
    int k = tile * PT + tid;
    if (k >= NPAIR) k = NPAIR - 1;
    int i = (int)((1.0f + sqrtf(1.0f + 8.0f * (float)k)) * 0.5f);
    while ((i * (i - 1)) / 2 > k) i--;
    while (((i + 1) * i) / 2 <= k) i++;
    si[tid] = i;
    sj[tid] = k - (i * (i - 1)) / 2;
  }
  b1s[tid] = b1[tid];
  w2s[tid] = w2[tid];
  __syncthreads();

  float acc[2][8][4];
#pragma unroll
  for (int mt = 0; mt < 2; mt++)
#pragma unroll
    for (int nt = 0; nt < 8; nt++)
#pragma unroll
      for (int e = 0; e < 4; e++) acc[mt][nt][e] = 0.f;

  // staging helper as a macro (writes chunk ch into stage buffer sbase)
#define STAGE_CHUNK(ch_, sbase_)                                              \
  do {                                                                        \
    int k0_ = (ch_) * 32;                                                     \
    _Pragma("unroll")                                                         \
    for (int t = 0; t < 4; t++) {                                             \
      int idx = tid + t * 256;                                                \
      int row = idx >> 4, kk2 = idx & 15;                                     \
      const float2 ea = *(const float2*)(emb + si[row] * DM + k0_ + 2 * kk2); \
      const float2 eb = *(const float2*)(emb + sj[row] * DM + k0_ + 2 * kk2); \
      float p0 = ea.x * eb.x, p1 = ea.y * eb.y;                               \
      __nv_bfloat16 h0 = __float2bfloat16(p0);                                \
      __nv_bfloat16 h1 = __float2bfloat16(p1);                                \
      __nv_bfloat16 l0 = __float2bfloat16(p0 - __bfloat162float(h0));         \
      __nv_bfloat16 l1 = __float2bfloat16(p1 - __bfloat162float(h1));         \
      uint32_t hp = ((uint32_t)*(uint16_t*)&h1 << 16) | *(uint16_t*)&h0;      \
      uint32_t lp = ((uint32_t)*(uint16_t*)&l1 << 16) | *(uint16_t*)&l0;      \
      *(uint32_t*)(smem + (sbase_) + SO_A_HI + row * 80 + kk2 * 4) = hp;      \
      *(uint32_t*)(smem + (sbase_) + SO_A_LO + row * 80 + kk2 * 4) = lp;      \
    }                                                                         \
    _Pragma("unroll")                                                         \
    for (int t = 0; t < 4; t++) {                                             \
      int idx = tid + t * 256;                                                \
      int n = idx >> 2, kg = idx & 3;                                         \
      uint4 hv = *(const uint4*)(g_w1t_hi + n * DM + k0_ + kg * 8);           \
      uint4 lv = *(const uint4*)(g_w1t_lo + n * DM + k0_ + kg * 8);           \
      *(uint4*)(smem + (sbase_) + SO_B_HI + n * 80 + kg * 16) = hv;           \
      *(uint4*)(smem + (sbase_) + SO_B_LO + n * 80 + kg * 16) = lv;           \
    }                                                                         \
  } while (0)

  // prologue: stage chunk 0 into buffer 0
  STAGE_CHUNK(0, 0);

  for (int ch = 0; ch < 8; ch++) {
    __syncthreads();  // stage[ch] complete (and buffer ch^1 free)
    uint32_t cur = (uint32_t)((ch & 1) * SBUF);
    // issue next chunk's staging first (loads overlap MMA below)
    if (ch < 7) {
      uint32_t nxt = (uint32_t)(((ch + 1) & 1) * SBUF);
      STAGE_CHUNK(ch + 1, nxt);
    }
    // MMA phase on current buffer
#pragma unroll
    for (int ks = 0; ks < 2; ks++) {
      uint32_t ah[2][4], al[2][4], bb[8][2];
      int arow = (lane & 7) + ((lane >> 3) & 1) * 8;
      int acolb = ks * 32 + ((lane >> 4) << 4);
#pragma unroll
      for (int mt = 0; mt < 2; mt++) {
        uint32_t ra = (uint32_t)((wm * 32 + mt * 16 + arow) * 80 + acolb);
        ldsm_x4(ah[mt], sb + cur + SO_A_HI + ra);
        ldsm_x4(al[mt], sb + cur + SO_A_LO + ra);
      }
      int bl_ = lane & 15;
      int brow = bl_ & 7;
      int bcolb = ks * 32 + ((bl_ >> 3) << 4);
#pragma unroll
      for (int nt = 0; nt < 8; nt++) {
        uint32_t rb = (uint32_t)((wn * 64 + nt * 8 + brow) * 80 + bcolb);
        ldsm_x2(bb[nt], sb + cur + SO_B_HI + rb);
      }
#pragma unroll
      for (int mt = 0; mt < 2; mt++)
#pragma unroll
        for (int nt = 0; nt < 8; nt++) mma16816(acc[mt][nt], ah[mt], bb[nt]);
#pragma unroll
      for (int mt = 0; mt < 2; mt++)
#pragma unroll
        for (int nt = 0; nt < 8; nt++) mma16816(acc[mt][nt], al[mt], bb[nt]);
#pragma unroll
      for (int nt = 0; nt < 8; nt++) {
        uint32_t rb = (uint32_t)((wn * 64 + nt * 8 + brow) * 80 + bcolb);
        ldsm_x2(bb[nt], sb + cur + SO_B_LO + rb);
      }
#pragma unroll
      for (int mt = 0; mt < 2; mt++)
#pragma unroll
        for (int nt = 0; nt < 8; nt++) mma16816(acc[mt][nt], ah[mt], bb[nt]);
    }
  }

  // Epilogue: relu(h + b1) . w2, quad shuffle-reduce, cross-warp reduce
#pragma unroll
  for (int mt = 0; mt < 2; mt++) {
#pragma unroll
    for (int half = 0; half < 2; half++) {
      float s = 0.f;
#pragma unroll
      for (int nt = 0; nt < 8; nt++) {
        int col = wn * 64 + nt * 8 + 2 * (lane & 3);
        float h0 = acc[mt][nt][half * 2 + 0] + b1s[col];
        float h1 = acc[mt][nt][half * 2 + 1] + b1s[col + 1];
        s = fmaf(fmaxf(h0, 0.f), w2s[col], s);
        s = fmaf(fmaxf(h1, 0.f), w2s[col + 1], s);
      }
      s += __shfl_xor_sync(0xffffffffu, s, 1);
      s += __shfl_xor_sync(0xffffffffu, s, 2);
      if ((lane & 3) == 0) {
        int row = wm * 32 + mt * 16 + half * 8 + (lane >> 2);
        red[row * 4 + wn] = s;
      }
    }
  }
  __syncthreads();
  if (tid < PT) {
    int k = tile * PT + tid;
    if (k < NPAIR) {
      float s = red[tid * 4] + red[tid * 4 + 1] + red[tid * 4 + 2] +
                red[tid * 4 + 3] + b2[0];
      float t = tanhf(s);
      int i = si[tid], j = sj[tid];
      g_R[(size_t)b * NA * NA + i * NA + j] = t;
      g_R[(size_t)b * NA * NA + j * NA + i] = t;
    }
  }
}

// ---------------------------------------------------------------------------
// PSD projection via HYBRID matrix-sign iteration:
//   11 quintic iters (symmetrize each), 4 cubic iters (symmetrize odd only),
//   R_psd = 0.5(X + X*S) + eps*I.  112^3 bf16 hi/lo 3-pass GEMMs.
// ---------------------------------------------------------------------------
#define QI 11
#define CI 4
#define QA 3.4445f
#define QB (-4.7750f)
#define QC 2.0315f
#define NSD 112
#define NS_THREADS 448
#define NS_TRI (NSD * (NSD + 1) / 2)
#define NPK 15
#define O_S32 0
#define O_SHI 50176
#define O_SLO 77056
#define O_YHI 103936
#define O_YLO 130816
#define O_THI 157696
#define O_TLO 184576
#define O_AUX 211456
#define SMEM_NS (211456 + 512 + 64)

__device__ __forceinline__ void gemm_ab(uint32_t sb, uint32_t oAh, uint32_t oAl,
                                        uint32_t oBh, uint32_t oBl,
                                        int wm, int wn, int lane,
                                        float (&acc)[7][4]) {
#pragma unroll
  for (int nt = 0; nt < 7; nt++)
#pragma unroll
    for (int e = 0; e < 4; e++) acc[nt][e] = 0.f;
#pragma unroll
  for (int ks = 0; ks < 7; ks++) {
    uint32_t ah[4], al[4], bb[7][2];
    int arow = (lane & 7) + ((lane >> 3) & 1) * 8;
    uint32_t ra = (uint32_t)((wm * 16 + arow) * 240 + ks * 32 + ((lane >> 4) << 4));
    ldsm_x4(ah, sb + oAh + ra);
    ldsm_x4(al, sb + oAl + ra);
    int bl_ = lane & 15;
    int brow = bl_ & 7;
    int bco = ks * 32 + ((bl_ >> 3) << 4);
#pragma unroll
    for (int nt = 0; nt < 7; nt++) {
      uint32_t rb = (uint32_t)((wn * 56 + nt * 8 + brow) * 240 + bco);
      ldsm_x2(bb[nt], sb + oBh + rb);
    }
#pragma unroll
    for (int nt = 0; nt < 7; nt++) mma16816(acc[nt], ah, bb[nt]);
#pragma unroll
    for (int nt = 0; nt < 7; nt++) mma16816(acc[nt], al, bb[nt]);
#pragma unroll
    for (int nt = 0; nt < 7; nt++) {
      uint32_t rb = (uint32_t)((wn * 56 + nt * 8 + brow) * 240 + bco);
      ldsm_x2(bb[nt], sb + oBl + rb);
    }
#pragma unroll
    for (int nt = 0; nt < 7; nt++) mma16816(acc[nt], ah, bb[nt]);
  }
}

__global__ __launch_bounds__(NS_THREADS) void psd_kernel(float* __restrict__ out) {
  extern __shared__ char smem[];
  uint32_t sb = smem_u32(smem);
  float* S32 = (float*)(smem + O_S32);
  float* aux = (float*)(smem + O_AUX);
  int b = blockIdx.x;
  int tid = threadIdx.x, lane = tid & 31, warp = tid >> 5;
  int wm = warp % 7, wn = warp / 7;
  const float* Rg = g_R + (size_t)b * NA * NA;

  int psi[NPK], psj[NPK];
#pragma unroll
  for (int k = 0; k < NPK; k++) {
    int idx = tid + k * NS_THREADS;
    if (idx < NS_TRI) {
      int i = (int)((sqrtf(8.f * (float)idx + 1.f) - 1.f) * 0.5f);
      while (i * (i + 1) / 2 > idx) i--;
      while ((i + 1) * (i + 2) / 2 <= idx) i++;
      psi[k] = i;
      psj[k] = idx - i * (i + 1) / 2;
    } else {
      psi[k] = 0;
      psj[k] = 0;
    }
  }

#define SYMMETRIZE_REFRESH()                                                  \
  do {                                                                        \
    _Pragma("unroll")                                                         \
    for (int k = 0; k < NPK; k++) {                                           \
      if (tid + k * NS_THREADS < NS_TRI) {                                    \
        int i = psi[k], j = psj[k];                                           \
        float avg = 0.5f * (S32[i * NSD + j] + S32[j * NSD + i]);             \
        avg = fminf(fmaxf(avg, -2.f), 2.f);                                   \
        S32[i * NSD + j] = avg;                                               \
        S32[j * NSD + i] = avg;                                               \
        __nv_bfloat16 h = __float2bfloat16(avg);                              \
        __nv_bfloat16 l = __float2bfloat16(avg - __bfloat162float(h));        \
        uint32_t oij = (uint32_t)(i * 240 + j * 2);                           \
        uint32_t oji = (uint32_t)(j * 240 + i * 2);                           \
        *(__nv_bfloat16*)(smem + O_SHI + oij) = h;                            \
        *(__nv_bfloat16*)(smem + O_SLO + oij) = l;                            \
        *(__nv_bfloat16*)(smem + O_SHI + oji) = h;                            \
        *(__nv_bfloat16*)(smem + O_SLO + oji) = l;                            \
      }                                                                       \
    }                                                                         \
  } while (0)

  float part = 0.f;
  for (int idx = tid; idx < NSD * NSD; idx += NS_THREADS) {
    int r = idx / NSD, c = idx - (idx / NSD) * NSD;
    float v = 0.f;
    if (r < NA && c < NA) v = (r == c) ? (1.0f - 1e-4f) : Rg[r * NA + c];
    S32[idx] = v;
    part += v * v;
  }
#pragma unroll
  for (int o = 16; o; o >>= 1) part += __shfl_xor_sync(0xffffffffu, part, o);
  if (lane == 0) aux[warp] = part;
  __syncthreads();
  if (tid == 0) {
    float s = 0.f;
    for (int w = 0; w < 14; w++) s += aux[w];
    float f = sqrtf(s);
    aux[14] = f;
    aux[15] = 1.0f / f;
  }
  __syncthreads();
  float fnorm = aux[14], invf = aux[15];

  for (int idx = tid; idx < NSD * NSD; idx += NS_THREADS) {
    int r = idx / NSD, c = idx - (idx / NSD) * NSD;
    float v = S32[idx] * invf;
    S32[idx] = v;
    __nv_bfloat16 h = __float2bfloat16(v);
    __nv_bfloat16 l = __float2bfloat16(v - __bfloat162float(h));
    uint32_t off = (uint32_t)(r * 240 + c * 2);
    *(__nv_bfloat16*)(smem + O_SHI + off) = h;
    *(__nv_bfloat16*)(smem + O_SLO + off) = l;
  }
  __syncthreads();

  float acc[7][4];

  // Phase 1: quintic
  for (int it = 0; it < QI; it++) {
    gemm_ab(sb, O_SHI, O_SLO, O_SHI, O_SLO, wm, wn, lane, acc);
#pragma unroll
    for (int nt = 0; nt < 7; nt++) {
#pragma unroll
      for (int half = 0; half < 2; half++) {
        int row = wm * 16 + (lane >> 2) + half * 8;
        int col = wn * 56 + nt * 8 + 2 * (lane & 3);
        float a0 = acc[nt][half * 2 + 0], a1 = acc[nt][half * 2 + 1];
        __nv_bfloat16 h0 = __float2bfloat16(a0), h1 = __float2bfloat16(a1);
        float r0 = a0 - __bfloat162float(h0), r1 = a1 - __bfloat162float(h1);
        uint32_t hp = ((uint32_t)*(uint16_t*)&h1 << 16) | *(uint16_t*)&h0;
        uint32_t lp = pack_bf16(r0, r1);
        *(uint32_t*)(smem + O_YHI + row * 240 + col * 2) = hp;
        *(uint32_t*)(smem + O_YLO + row * 240 + col * 2) = lp;
      }
    }
    __syncthreads();
    gemm_ab(sb, O_YHI, O_YLO, O_YHI, O_YLO, wm, wn, lane, acc);
    __syncthreads();
#pragma unroll
    for (int nt = 0; nt < 7; nt++) {
#pragma unroll
      for (int half = 0; half < 2; half++) {
        int row = wm * 16 + (lane >> 2) + half * 8;
        int col = wn * 56 + nt * 8 + 2 * (lane & 3);
        float t01[2];
#pragma unroll
        for (int j = 0; j < 2; j++) {
          int c = col + j;
          uint32_t off = (uint32_t)(row * 240 + c * 2);
          float y = __bfloat162float(*(__nv_bfloat16*)(smem + O_YHI + off)) +
                    __bfloat162float(*(__nv_bfloat16*)(smem + O_YLO + off));
          t01[j] = ((row == c) ? QA : 0.f) + QB * y + QC * acc[nt][half * 2 + j];
        }
        __nv_bfloat16 h0 = __float2bfloat16(t01[0]), h1 = __float2bfloat16(t01[1]);
        float r0 = t01[0] - __bfloat162float(h0), r1 = t01[1] - __bfloat162float(h1);
        uint32_t hp = ((uint32_t)*(uint16_t*)&h1 << 16) | *(uint16_t*)&h0;
        uint32_t lp = pack_bf16(r0, r1);
        *(uint32_t*)(smem + O_THI + row * 240 + col * 2) = hp;
        *(uint32_t*)(smem + O_TLO + row * 240 + col * 2) = lp;
      }
    }
    __syncthreads();
    gemm_ab(sb, O_SHI, O_SLO, O_THI, O_TLO, wm, wn, lane, acc);
    __syncthreads();
#pragma unroll
    for (int nt = 0; nt < 7; nt++) {
#pragma unroll
      for (int half = 0; half < 2; half++) {
        int row = wm * 16 + (lane >> 2) + half * 8;
        int col = wn * 56 + nt * 8 + 2 * (lane & 3);
        int i0 = row * NSD + col;
        S32[i0]     = acc[nt][half * 2 + 0];
        S32[i0 + 1] = acc[nt][half * 2 + 1];
      }
    }
    __syncthreads();
    SYMMETRIZE_REFRESH();
    __syncthreads();
  }

  // Phase 2: cubic polish (symmetrize on odd iters only)
  for (int it = 0; it < CI; it++) {
    gemm_ab(sb, O_SHI, O_SLO, O_SHI, O_SLO, wm, wn, lane, acc);
#pragma unroll
    for (int nt = 0; nt < 7; nt++) {
#pragma unroll
      for (int half = 0; half < 2; half++) {
        int row = wm * 16 + (lane >> 2) + half * 8;
        int col = wn * 56 + nt * 8 + 2 * (lane & 3);
        float a0 = acc[nt][half * 2 + 0], a1 = acc[nt][half * 2 + 1];
        __nv_bfloat16 h0 = __float2bfloat16(a0), h1 = __float2bfloat16(a1);
        float r0 = a0 - __bfloat162float(h0), r1 = a1 - __bfloat162float(h1);
        uint32_t hp = ((uint32_t)*(uint16_t*)&h1 << 16) | *(uint16_t*)&h0;
        uint32_t lp = pack_bf16(r0, r1);
        *(uint32_t*)(smem + O_YHI + row * 240 + col * 2) = hp;
        *(uint32_t*)(smem + O_YLO + row * 240 + col * 2) = lp;
      }
    }
    __syncthreads();
    gemm_ab(sb, O_SHI, O_SLO, O_YHI, O_YLO, wm, wn, lane, acc);
    __syncthreads();
    if (it & 1) {
#pragma unroll
      for (int nt = 0; nt < 7; nt++) {
#pragma unroll
        for (int half = 0; half < 2; half++) {
          int row = wm * 16 + (lane >> 2) + half * 8;
          int col = wn * 56 + nt * 8 + 2 * (lane & 3);
          int i0 = row * NSD + col;
          S32[i0]     = 1.5f * S32[i0]     - 0.5f * acc[nt][half * 2 + 0];
          S32[i0 + 1] = 1.5f * S32[i0 + 1] - 0.5f * acc[nt][half * 2 + 1];
        }
      }
      __syncthreads();
      SYMMETRIZE_REFRESH();
    } else {
#pragma unroll
      for (int nt = 0; nt < 7; nt++) {
#pragma unroll
        for (int half = 0; half < 2; half++) {
          int row = wm * 16 + (lane >> 2) + half * 8;
          int col = wn * 56 + nt * 8 + 2 * (lane & 3);
          int i0 = row * NSD + col;
          float s0 = 1.5f * S32[i0]     - 0.5f * acc[nt][half * 2 + 0];
          float s1 = 1.5f * S32[i0 + 1] - 0.5f * acc[nt][half * 2 + 1];
          S32[i0] = s0;
          S32[i0 + 1] = s1;
          __nv_bfloat16 h0 = __float2bfloat16(s0), h1 = __float2bfloat16(s1);
          float r0 = s0 - __bfloat162float(h0), r1 = s1 - __bfloat162float(h1);
          uint32_t hp = ((uint32_t)*(uint16_t*)&h1 << 16) | *(uint16_t*)&h0;
          uint32_t lp = pack_bf16(r0, r1);
          *(uint32_t*)(smem + O_SHI + row * 240 + col * 2) = hp;
          *(uint32_t*)(smem + O_SLO + row * 240 + col * 2) = lp;
        }
      }
    }
    __syncthreads();
  }

  // final: W = S*Xn ; P = 0.5(X + f*W) + eps*I
  for (int idx = tid; idx < NSD * NSD; idx += NS_THREADS) {
    int r = idx / NSD, c = idx - (idx / NSD) * NSD;
    float v = 0.f;
    if (r < NA && c < NA)
      v = ((r == c) ? (1.0f - 1e-4f) : Rg[r * NA + c]) * invf;
    __nv_bfloat16 h = __float2bfloat16(v);
    __nv_bfloat16 l = __float2bfloat16(v - __bfloat162float(h));
    uint32_t off = (uint32_t)(r * 240 + c * 2);
    *(__nv_bfloat16*)(smem + O_YHI + off) = h;
    *(__nv_bfloat16*)(smem + O_YLO + off) = l;
  }
  __syncthreads();
  gemm_ab(sb, O_SHI, O_SLO, O_YHI, O_YLO, wm, wn, lane, acc);
  __syncthreads();
#pragma unroll
  for (int nt = 0; nt < 7; nt++) {
#pragma unroll
    for (int half = 0; half < 2; half++) {
      int row = wm * 16 + (lane >> 2) + half * 8;
      int col = wn * 56 + nt * 8 + 2 * (lane & 3);
#pragma unroll
      for (int j = 0; j < 2; j++) {
        int c = col + j;
        float Xg = 0.f;
        if (row < NA && c < NA)
          Xg = (row == c) ? (1.0f - 1e-4f) : Rg[row * NA + c];
        float P = 0.5f * (Xg + fnorm * acc[nt][half * 2 + j]) +
                  ((row == c) ? 1e-4f : 0.f);
        S32[row * NSD + c] = P;
      }
    }
  }
  __syncthreads();

  if (tid < NA) aux[16 + tid] = rsqrtf(fmaxf(S32[tid * (NSD + 1)], 1e-6f));
  __syncthreads();

  const float* vl = g_vols + b * NA;
  float* og = out + (size_t)b * NA * NA;
  for (int idx = tid; idx < NA * NA; idx += NS_THREADS) {
    int r = idx / NA, c = idx - (idx / NA) * NA;
    og[idx] = vl[r] * vl[c] * aux[16 + r] * aux[16 + c] * S32[r * NSD + c];
  }
}

// ---------------------------------------------------------------------------
extern "C" void kernel_launch(void* const* d_in, const int* in_sizes, int n_in,
                              void* d_out, int out_size) {
  const float* x   = (const float*)d_in[0];
  const float* vw1 = (const float*)d_in[1];
  const float* vb1 = (const float*)d_in[2];
  const float* vw2 = (const float*)d_in[3];
  const float* vb2 = (const float*)d_in[4];
  const float* cw1 = (const float*)d_in[5];
  const float* cb1 = (const float*)d_in[6];
  const float* cw2 = (const float*)d_in[7];
  const float* cb2 = (const float*)d_in[8];
  float* out = (float*)d_out;

  prep_w1t<<<HID, DM>>>(cw1);

  cudaFuncSetAttribute(pair_mma_kernel,
                       cudaFuncAttributeMaxDynamicSharedMemorySize, SMEM_PAIR);
  pair_mma_kernel<<<dim3(PTILES + VTILES, BATCH), 256, SMEM_PAIR>>>(
      x, vw1, vb1, vw2, vb2, cb1, cw2, cb2);

  cudaFuncSetAttribute(psd_kernel,
                       cudaFuncAttributeMaxDynamicSharedMemorySize, SMEM_NS);
  psd_kernel<<<BATCH, NS_THREADS, SMEM_NS>>>(out);
}

// round 15
// speedup vs baseline: 1.0507x; 1.0507x over previous
#include <cuda_runtime.h>
#include <cuda_bf16.h>
#include <math.h>
#include <stdint.h>

#define NA 100
#define DM 256
#define HID 256
#define BATCH 64
#define NPAIR 4950
#define PT 64           // pairs per CTA tile
#define PTILES 78       // ceil(4950/64)
#define VTILES 7        // vols row-groups of 16

// ---------------- device scratch (no allocation allowed) ----------------
__device__ float g_R[BATCH * NA * NA];
__device__ float g_vols[BATCH * NA];
__device__ __nv_bfloat16 g_w1t_hi[HID * DM];  // [n][k] K-major
__device__ __nv_bfloat16 g_w1t_lo[HID * DM];

__device__ __forceinline__ uint32_t smem_u32(const void* p) {
  uint32_t a;
  asm("{ .reg .u64 t; cvta.to.shared.u64 t, %1; cvt.u32.u64 %0, t; }"
      : "=r"(a) : "l"(p));
  return a;
}
__device__ __forceinline__ void ldsm_x4(uint32_t (&r)[4], uint32_t addr) {
  asm volatile(
      "ldmatrix.sync.aligned.m8n8.x4.shared.b16 {%0,%1,%2,%3}, [%4];"
      : "=r"(r[0]), "=r"(r[1]), "=r"(r[2]), "=r"(r[3]) : "r"(addr));
}
__device__ __forceinline__ void ldsm_x2(uint32_t (&r)[2], uint32_t addr) {
  asm volatile(
      "ldmatrix.sync.aligned.m8n8.x2.shared.b16 {%0,%1}, [%2];"
      : "=r"(r[0]), "=r"(r[1]) : "r"(addr));
}
__device__ __forceinline__ void mma16816(float (&d)[4], const uint32_t (&a)[4],
                                         const uint32_t (&b)[2]) {
  asm volatile(
      "mma.sync.aligned.m16n8k16.row.col.f32.bf16.bf16.f32 "
      "{%0,%1,%2,%3}, {%4,%5,%6,%7}, {%8,%9}, {%0,%1,%2,%3};"
      : "+f"(d[0]), "+f"(d[1]), "+f"(d[2]), "+f"(d[3])
      : "r"(a[0]), "r"(a[1]), "r"(a[2]), "r"(a[3]), "r"(b[0]), "r"(b[1]));
}
__device__ __forceinline__ uint32_t pack_bf16(float a, float b) {
  __nv_bfloat16 h0 = __float2bfloat16(a), h1 = __float2bfloat16(b);
  return ((uint32_t)*(uint16_t*)&h1 << 16) | *(uint16_t*)&h0;
}
__device__ __forceinline__ void cp_async16(uint32_t dst, const void* src) {
  asm volatile("cp.async.ca.shared.global [%0], [%1], 16;"
               :: "r"(dst), "l"(src) : "memory");
}
#define CP_COMMIT() asm volatile("cp.async.commit_group;" ::: "memory")
#define CP_WAIT0()  asm volatile("cp.async.wait_group 0;" ::: "memory")

// ---------------------------------------------------------------------------
__global__ void prep_w1t(const float* __restrict__ w1) {
  int n = blockIdx.x, k = threadIdx.x;
  float v = w1[k * HID + n];
  __nv_bfloat16 h = __float2bfloat16(v);
  float r = v - __bfloat162float(h);
  g_w1t_hi[n * DM + k] = h;
  g_w1t_lo[n * DM + k] = __float2bfloat16(r);
}

// ---------------------------------------------------------------------------
// FUSED pair MLP (tiles 0..77) + vols MLP (tiles 78..84), per batch.
// pair: mma.sync bf16 2-way split, 3 passes, double-buffered, B via cp.async,
// A staged with float4 loads. LSU ops halved vs prior round.
// ---------------------------------------------------------------------------
#define SBUF 51200     // bytes per stage
#define SO_A_HI 0
#define SO_A_LO 5120
#define SO_B_HI 10240
#define SO_B_LO 30720
#define OFF_SI  102400
#define OFF_SJ  102656
#define OFF_B1  102912
#define OFF_W2  103936
#define OFF_RED 104960
#define SMEM_PAIR 105984

__global__ __launch_bounds__(256, 2) void pair_mma_kernel(
    const float* __restrict__ x,
    const float* __restrict__ vw1, const float* __restrict__ vb1,
    const float* __restrict__ vw2, const float* __restrict__ vb2,
    const float* __restrict__ b1, const float* __restrict__ w2,
    const float* __restrict__ b2) {
  extern __shared__ char smem[];
  uint32_t sb = smem_u32(smem);
  int b = blockIdx.y, tile = blockIdx.x;
  int tid = threadIdx.x, lane = tid & 31, warp = tid >> 5;
  const float* emb = x + ((size_t)b * 64 + 63) * NA * DM;

  if (tile >= PTILES) {
    // ================= vols branch =================
    int r0 = (tile - PTILES) * 16;
    float* es = (float*)smem;                  // [16][256]
    float* red = (float*)(smem + 16 * DM * 4); // [16][8]

    for (int idx = tid; idx < 16 * DM; idx += 256) {
      int r = idx >> 8, d = idx & 255;
      es[r * DM + d] = (r0 + r < NA) ? emb[(r0 + r) * DM + d] : 0.f;
    }
    __syncthreads();

    float acc[16];
    float bb = vb1[tid];
#pragma unroll
    for (int r = 0; r < 16; r++) acc[r] = bb;

#pragma unroll 4
    for (int d = 0; d < DM; d++) {
      float w = vw1[d * HID + tid];
#pragma unroll
      for (int r = 0; r < 16; r++) acc[r] = fmaf(es[r * DM + d], w, acc[r]);
    }

    float wv = vw2[tid];
#pragma unroll
    for (int r = 0; r < 16; r++) {
      float v = fmaxf(acc[r], 0.f) * wv;
#pragma unroll
      for (int o = 16; o; o >>= 1) v += __shfl_xor_sync(0xffffffffu, v, o);
      if (lane == 0) red[r * 8 + warp] = v;
    }
    __syncthreads();
    if (tid < 16) {
      float s = 0.f;
#pragma unroll
      for (int w = 0; w < 8; w++) s += red[tid * 8 + w];
      s += vb2[0];
      float sp = fmaxf(s, 0.f) + log1pf(expf(-fabsf(s)));
      if (r0 + tid < NA) g_vols[b * NA + r0 + tid] = sp + 1e-6f;
    }
    return;
  }

  // ================= pair branch =================
  int wm = warp >> 2, wn = warp & 3;   // 2 x 4 warps

  int* si = (int*)(smem + OFF_SI);
  int* sj = (int*)(smem + OFF_SJ);
  float* b1s = (float*)(smem + OFF_B1);
  float* w2s = (float*)(smem + OFF_W2);
  float* red = (float*)(smem + OFF_RED);

  if (tid < PT) {
    int k = tile * PT + tid;
    if (k >= NPAIR) k = NPAIR - 1;
    int i = (int)((1.0f + sqrtf(1.0f + 8.0f * (float)k)) * 0.5f);
    while ((i * (i - 1)) / 2 > k) i--;
    while (((i + 1) * i) / 2 <= k) i++;
    si[tid] = i;
    sj[tid] = k - (i * (i - 1)) / 2;
  }
  b1s[tid] = b1[tid];
  w2s[tid] = w2[tid];
  __syncthreads();

  float acc[2][8][4];
#pragma unroll
  for (int mt = 0; mt < 2; mt++)
#pragma unroll
    for (int nt = 0; nt < 8; nt++)
#pragma unroll
      for (int e = 0; e < 4; e++) acc[mt][nt][e] = 0.f;

  // staging: B first via cp.async (overlaps A compute + MMA), then A float4.
#define STAGE_CHUNK(ch_, sbase_)                                              \
  do {                                                                        \
    int k0_ = (ch_) * 32;                                                     \
    _Pragma("unroll")                                                         \
    for (int t = 0; t < 4; t++) {                                             \
      int idx = tid + t * 256;                                                \
      int n = idx >> 2, kg = idx & 3;                                         \
      cp_async16(sb + (sbase_) + SO_B_HI + n * 80 + kg * 16,                  \
                 g_w1t_hi + n * DM + k0_ + kg * 8);                           \
      cp_async16(sb + (sbase_) + SO_B_LO + n * 80 + kg * 16,                  \
                 g_w1t_lo + n * DM + k0_ + kg * 8);                           \
    }                                                                         \
    CP_COMMIT();                                                              \
    _Pragma("unroll")                                                         \
    for (int t = 0; t < 2; t++) {                                             \
      int idx = tid + t * 256;                                                \
      int row = idx >> 3, kk4 = idx & 7;                                      \
      const float4 ea = *(const float4*)(emb + si[row] * DM + k0_ + 4 * kk4); \
      const float4 eb = *(const float4*)(emb + sj[row] * DM + k0_ + 4 * kk4); \
      float p0 = ea.x * eb.x, p1 = ea.y * eb.y;                               \
      float p2 = ea.z * eb.z, p3 = ea.w * eb.w;                               \
      __nv_bfloat16 h0 = __float2bfloat16(p0);                                \
      __nv_bfloat16 h1 = __float2bfloat16(p1);                                \
      __nv_bfloat16 h2 = __float2bfloat16(p2);                                \
      __nv_bfloat16 h3 = __float2bfloat16(p3);                                \
      uint32_t hp0 = ((uint32_t)*(uint16_t*)&h1 << 16) | *(uint16_t*)&h0;     \
      uint32_t hp1 = ((uint32_t)*(uint16_t*)&h3 << 16) | *(uint16_t*)&h2;     \
      uint32_t lp0 = pack_bf16(p0 - __bfloat162float(h0),                     \
                               p1 - __bfloat162float(h1));                    \
      uint32_t lp1 = pack_bf16(p2 - __bfloat162float(h2),                     \
                               p3 - __bfloat162float(h3));                    \
      *(uint2*)(smem + (sbase_) + SO_A_HI + row * 80 + kk4 * 8) =             \
          make_uint2(hp0, hp1);                                               \
      *(uint2*)(smem + (sbase_) + SO_A_LO + row * 80 + kk4 * 8) =             \
          make_uint2(lp0, lp1);                                               \
    }                                                                         \
  } while (0)

  // prologue: stage chunk 0 into buffer 0
  STAGE_CHUNK(0, 0);

  for (int ch = 0; ch < 8; ch++) {
    CP_WAIT0();
    __syncthreads();  // stage[ch] complete (and buffer ch^1 free)
    uint32_t cur = (uint32_t)((ch & 1) * SBUF);
    if (ch < 7) {
      uint32_t nxt = (uint32_t)(((ch + 1) & 1) * SBUF);
      STAGE_CHUNK(ch + 1, nxt);
    }
    // MMA phase on current buffer
#pragma unroll
    for (int ks = 0; ks < 2; ks++) {
      uint32_t ah[2][4], al[2][4], bb[8][2];
      int arow = (lane & 7) + ((lane >> 3) & 1) * 8;
      int acolb = ks * 32 + ((lane >> 4) << 4);
#pragma unroll
      for (int mt = 0; mt < 2; mt++) {
        uint32_t ra = (uint32_t)((wm * 32 + mt * 16 + arow) * 80 + acolb);
        ldsm_x4(ah[mt], sb + cur + SO_A_HI + ra);
        ldsm_x4(al[mt], sb + cur + SO_A_LO + ra);
      }
      int bl_ = lane & 15;
      int brow = bl_ & 7;
      int bcolb = ks * 32 + ((bl_ >> 3) << 4);
#pragma unroll
      for (int nt = 0; nt < 8; nt++) {
        uint32_t rb = (uint32_t)((wn * 64 + nt * 8 + brow) * 80 + bcolb);
        ldsm_x2(bb[nt], sb + cur + SO_B_HI + rb);
      }
#pragma unroll
      for (int mt = 0; mt < 2; mt++)
#pragma unroll
        for (int nt = 0; nt < 8; nt++) mma16816(acc[mt][nt], ah[mt], bb[nt]);
#pragma unroll
      for (int mt = 0; mt < 2; mt++)
#pragma unroll
        for (int nt = 0; nt < 8; nt++) mma16816(acc[mt][nt], al[mt], bb[nt]);
#pragma unroll
      for (int nt = 0; nt < 8; nt++) {
        uint32_t rb = (uint32_t)((wn * 64 + nt * 8 + brow) * 80 + bcolb);
        ldsm_x2(bb[nt], sb + cur + SO_B_LO + rb);
      }
#pragma unroll
      for (int mt = 0; mt < 2; mt++)
#pragma unroll
        for (int nt = 0; nt < 8; nt++) mma16816(acc[mt][nt], ah[mt], bb[nt]);
    }
  }

  // Epilogue: relu(h + b1) . w2, quad shuffle-reduce, cross-warp reduce
#pragma unroll
  for (int mt = 0; mt < 2; mt++) {
#pragma unroll
    for (int half = 0; half < 2; half++) {
      float s = 0.f;
#pragma unroll
      for (int nt = 0; nt < 8; nt++) {
        int col = wn * 64 + nt * 8 + 2 * (lane & 3);
        float h0 = acc[mt][nt][half * 2 + 0] + b1s[col];
        float h1 = acc[mt][nt][half * 2 + 1] + b1s[col + 1];
        s = fmaf(fmaxf(h0, 0.f), w2s[col], s);
        s = fmaf(fmaxf(h1, 0.f), w2s[col + 1], s);
      }
      s += __shfl_xor_sync(0xffffffffu, s, 1);
      s += __shfl_xor_sync(0xffffffffu, s, 2);
      if ((lane & 3) == 0) {
        int row = wm * 32 + mt * 16 + half * 8 + (lane >> 2);
        red[row * 4 + wn] = s;
      }
    }
  }
  __syncthreads();
  if (tid < PT) {
    int k = tile * PT + tid;
    if (k < NPAIR) {
      float s = red[tid * 4] + red[tid * 4 + 1] + red[tid * 4 + 2] +
                red[tid * 4 + 3] + b2[0];
      float t = tanhf(s);
      int i = si[tid], j = sj[tid];
      g_R[(size_t)b * NA * NA + i * NA + j] = t;
      g_R[(size_t)b * NA * NA + j * NA + i] = t;
    }
  }
}

// ---------------------------------------------------------------------------
// PSD projection via HYBRID matrix-sign iteration:
//   11 quintic iters (symmetrize each), 4 cubic iters (symmetrize odd only),
//   R_psd = 0.5(X + X*S) + eps*I.  112^3 bf16 hi/lo 3-pass GEMMs.
// ---------------------------------------------------------------------------
#define QI 11
#define CI 4
#define QA 3.4445f
#define QB (-4.7750f)
#define QC 2.0315f
#define NSD 112
#define NS_THREADS 448
#define NS_TRI (NSD * (NSD + 1) / 2)
#define NPK 15
#define O_S32 0
#define O_SHI 50176
#define O_SLO 77056
#define O_YHI 103936
#define O_YLO 130816
#define O_THI 157696
#define O_TLO 184576
#define O_AUX 211456
#define SMEM_NS (211456 + 512 + 64)

__device__ __forceinline__ void gemm_ab(uint32_t sb, uint32_t oAh, uint32_t oAl,
                                        uint32_t oBh, uint32_t oBl,
                                        int wm, int wn, int lane,
                                        float (&acc)[7][4]) {
#pragma unroll
  for (int nt = 0; nt < 7; nt++)
#pragma unroll
    for (int e = 0; e < 4; e++) acc[nt][e] = 0.f;
#pragma unroll
  for (int ks = 0; ks < 7; ks++) {
    uint32_t ah[4], al[4], bb[7][2];
    int arow = (lane & 7) + ((lane >> 3) & 1) * 8;
    uint32_t ra = (uint32_t)((wm * 16 + arow) * 240 + ks * 32 + ((lane >> 4) << 4));
    ldsm_x4(ah, sb + oAh + ra);
    ldsm_x4(al, sb + oAl + ra);
    int bl_ = lane & 15;
    int brow = bl_ & 7;
    int bco = ks * 32 + ((bl_ >> 3) << 4);
#pragma unroll
    for (int nt = 0; nt < 7; nt++) {
      uint32_t rb = (uint32_t)((wn * 56 + nt * 8 + brow) * 240 + bco);
      ldsm_x2(bb[nt], sb + oBh + rb);
    }
#pragma unroll
    for (int nt = 0; nt < 7; nt++) mma16816(acc[nt], ah, bb[nt]);
#pragma unroll
    for (int nt = 0; nt < 7; nt++) mma16816(acc[nt], al, bb[nt]);
#pragma unroll
    for (int nt = 0; nt < 7; nt++) {
      uint32_t rb = (uint32_t)((wn * 56 + nt * 8 + brow) * 240 + bco);
      ldsm_x2(bb[nt], sb + oBl + rb);
    }
#pragma unroll
    for (int nt = 0; nt < 7; nt++) mma16816(acc[nt], ah, bb[nt]);
  }
}

__global__ __launch_bounds__(NS_THREADS) void psd_kernel(float* __restrict__ out) {
  extern __shared__ char smem[];
  uint32_t sb = smem_u32(smem);
  float* S32 = (float*)(smem + O_S32);
  float* aux = (float*)(smem + O_AUX);
  int b = blockIdx.x;
  int tid = threadIdx.x, lane = tid & 31, warp = tid >> 5;
  int wm = warp % 7, wn = warp / 7;
  const float* Rg = g_R + (size_t)b * NA * NA;

  int psi[NPK], psj[NPK];
#pragma unroll
  for (int k = 0; k < NPK; k++) {
    int idx = tid + k * NS_THREADS;
    if (idx < NS_TRI) {
      int i = (int)((sqrtf(8.f * (float)idx + 1.f) - 1.f) * 0.5f);
      while (i * (i + 1) / 2 > idx) i--;
      while ((i + 1) * (i + 2) / 2 <= idx) i++;
      psi[k] = i;
      psj[k] = idx - i * (i + 1) / 2;
    } else {
      psi[k] = 0;
      psj[k] = 0;
    }
  }

#define SYMMETRIZE_REFRESH()                                                  \
  do {                                                                        \
    _Pragma("unroll")                                                         \
    for (int k = 0; k < NPK; k++) {                                           \
      if (tid + k * NS_THREADS < NS_TRI) {                                    \
        int i = psi[k], j = psj[k];                                           \
        float avg = 0.5f * (S32[i * NSD + j] + S32[j * NSD + i]);             \
        avg = fminf(fmaxf(avg, -2.f), 2.f);                                   \
        S32[i * NSD + j] = avg;                                               \
        S32[j * NSD + i] = avg;                                               \
        __nv_bfloat16 h = __float2bfloat16(avg);                              \
        __nv_bfloat16 l = __float2bfloat16(avg - __bfloat162float(h));        \
        uint32_t oij = (uint32_t)(i * 240 + j * 2);                           \
        uint32_t oji = (uint32_t)(j * 240 + i * 2);                           \
        *(__nv_bfloat16*)(smem + O_SHI + oij) = h;                            \
        *(__nv_bfloat16*)(smem + O_SLO + oij) = l;                            \
        *(__nv_bfloat16*)(smem + O_SHI + oji) = h;                            \
        *(__nv_bfloat16*)(smem + O_SLO + oji) = l;                            \
      }                                                                       \
    }                                                                         \
  } while (0)

  float part = 0.f;
  for (int idx = tid; idx < NSD * NSD; idx += NS_THREADS) {
    int r = idx / NSD, c = idx - (idx / NSD) * NSD;
    float v = 0.f;
    if (r < NA && c < NA) v = (r == c) ? (1.0f - 1e-4f) : Rg[r * NA + c];
    S32[idx] = v;
    part += v * v;
  }
#pragma unroll
  for (int o = 16; o; o >>= 1) part += __shfl_xor_sync(0xffffffffu, part, o);
  if (lane == 0) aux[warp] = part;
  __syncthreads();
  if (tid == 0) {
    float s = 0.f;
    for (int w = 0; w < 14; w++) s += aux[w];
    float f = sqrtf(s);
    aux[14] = f;
    aux[15] = 1.0f / f;
  }
  __syncthreads();
  float fnorm = aux[14], invf = aux[15];

  for (int idx = tid; idx < NSD * NSD; idx += NS_THREADS) {
    int r = idx / NSD, c = idx - (idx / NSD) * NSD;
    float v = S32[idx] * invf;
    S32[idx] = v;
    __nv_bfloat16 h = __float2bfloat16(v);
    __nv_bfloat16 l = __float2bfloat16(v - __bfloat162float(h));
    uint32_t off = (uint32_t)(r * 240 + c * 2);
    *(__nv_bfloat16*)(smem + O_SHI + off) = h;
    *(__nv_bfloat16*)(smem + O_SLO + off) = l;
  }
  __syncthreads();

  float acc[7][4];

  // Phase 1: quintic
  for (int it = 0; it < QI; it++) {
    gemm_ab(sb, O_SHI, O_SLO, O_SHI, O_SLO, wm, wn, lane, acc);
#pragma unroll
    for (int nt = 0; nt < 7; nt++) {
#pragma unroll
      for (int half = 0; half < 2; half++) {
        int row = wm * 16 + (lane >> 2) + half * 8;
        int col = wn * 56 + nt * 8 + 2 * (lane & 3);
        float a0 = acc[nt][half * 2 + 0], a1 = acc[nt][half * 2 + 1];
        __nv_bfloat16 h0 = __float2bfloat16(a0), h1 = __float2bfloat16(a1);
        float r0 = a0 - __bfloat162float(h0), r1 = a1 - __bfloat162float(h1);
        uint32_t hp = ((uint32_t)*(uint16_t*)&h1 << 16) | *(uint16_t*)&h0;
        uint32_t lp = pack_bf16(r0, r1);
        *(uint32_t*)(smem + O_YHI + row * 240 + col * 2) = hp;
        *(uint32_t*)(smem + O_YLO + row * 240 + col * 2) = lp;
      }
    }
    __syncthreads();
    gemm_ab(sb, O_YHI, O_YLO, O_YHI, O_YLO, wm, wn, lane, acc);
    __syncthreads();
#pragma unroll
    for (int nt = 0; nt < 7; nt++) {
#pragma unroll
      for (int half = 0; half < 2; half++) {
        int row = wm * 16 + (lane >> 2) + half * 8;
        int col = wn * 56 + nt * 8 + 2 * (lane & 3);
        float t01[2];
#pragma unroll
        for (int j = 0; j < 2; j++) {
          int c = col + j;
          uint32_t off = (uint32_t)(row * 240 + c * 2);
          float y = __bfloat162float(*(__nv_bfloat16*)(smem + O_YHI + off)) +
                    __bfloat162float(*(__nv_bfloat16*)(smem + O_YLO + off));
          t01[j] = ((row == c) ? QA : 0.f) + QB * y + QC * acc[nt][half * 2 + j];
        }
        __nv_bfloat16 h0 = __float2bfloat16(t01[0]), h1 = __float2bfloat16(t01[1]);
        float r0 = t01[0] - __bfloat162float(h0), r1 = t01[1] - __bfloat162float(h1);
        uint32_t hp = ((uint32_t)*(uint16_t*)&h1 << 16) | *(uint16_t*)&h0;
        uint32_t lp = pack_bf16(r0, r1);
        *(uint32_t*)(smem + O_THI + row * 240 + col * 2) = hp;
        *(uint32_t*)(smem + O_TLO + row * 240 + col * 2) = lp;
      }
    }
    __syncthreads();
    gemm_ab(sb, O_SHI, O_SLO, O_THI, O_TLO, wm, wn, lane, acc);
    __syncthreads();
#pragma unroll
    for (int nt = 0; nt < 7; nt++) {
#pragma unroll
      for (int half = 0; half < 2; half++) {
        int row = wm * 16 + (lane >> 2) + half * 8;
        int col = wn * 56 + nt * 8 + 2 * (lane & 3);
        int i0 = row * NSD + col;
        S32[i0]     = acc[nt][half * 2 + 0];
        S32[i0 + 1] = acc[nt][half * 2 + 1];
      }
    }
    __syncthreads();
    SYMMETRIZE_REFRESH();
    __syncthreads();
  }

  // Phase 2: cubic polish (symmetrize on odd iters only)
  for (int it = 0; it < CI; it++) {
    gemm_ab(sb, O_SHI, O_SLO, O_SHI, O_SLO, wm, wn, lane, acc);
#pragma unroll
    for (int nt = 0; nt < 7; nt++) {
#pragma unroll
      for (int half = 0; half < 2; half++) {
        int row = wm * 16 + (lane >> 2) + half * 8;
        int col = wn * 56 + nt * 8 + 2 * (lane & 3);
        float a0 = acc[nt][half * 2 + 0], a1 = acc[nt][half * 2 + 1];
        __nv_bfloat16 h0 = __float2bfloat16(a0), h1 = __float2bfloat16(a1);
        float r0 = a0 - __bfloat162float(h0), r1 = a1 - __bfloat162float(h1);
        uint32_t hp = ((uint32_t)*(uint16_t*)&h1 << 16) | *(uint16_t*)&h0;
        uint32_t lp = pack_bf16(r0, r1);
        *(uint32_t*)(smem + O_YHI + row * 240 + col * 2) = hp;
        *(uint32_t*)(smem + O_YLO + row * 240 + col * 2) = lp;
      }
    }
    __syncthreads();
    gemm_ab(sb, O_SHI, O_SLO, O_YHI, O_YLO, wm, wn, lane, acc);
    __syncthreads();
    if (it & 1) {
#pragma unroll
      for (int nt = 0; nt < 7; nt++) {
#pragma unroll
        for (int half = 0; half < 2; half++) {
          int row = wm * 16 + (lane >> 2) + half * 8;
          int col = wn * 56 + nt * 8 + 2 * (lane & 3);
          int i0 = row * NSD + col;
          S32[i0]     = 1.5f * S32[i0]     - 0.5f * acc[nt][half * 2 + 0];
          S32[i0 + 1] = 1.5f * S32[i0 + 1] - 0.5f * acc[nt][half * 2 + 1];
        }
      }
      __syncthreads();
      SYMMETRIZE_REFRESH();
    } else {
#pragma unroll
      for (int nt = 0; nt < 7; nt++) {
#pragma unroll
        for (int half = 0; half < 2; half++) {
          int row = wm * 16 + (lane >> 2) + half * 8;
          int col = wn * 56 + nt * 8 + 2 * (lane & 3);
          int i0 = row * NSD + col;
          float s0 = 1.5f * S32[i0]     - 0.5f * acc[nt][half * 2 + 0];
          float s1 = 1.5f * S32[i0 + 1] - 0.5f * acc[nt][half * 2 + 1];
          S32[i0] = s0;
          S32[i0 + 1] = s1;
          __nv_bfloat16 h0 = __float2bfloat16(s0), h1 = __float2bfloat16(s1);
          float r0 = s0 - __bfloat162float(h0), r1 = s1 - __bfloat162float(h1);
          uint32_t hp = ((uint32_t)*(uint16_t*)&h1 << 16) | *(uint16_t*)&h0;
          uint32_t lp = pack_bf16(r0, r1);
          *(uint32_t*)(smem + O_SHI + row * 240 + col * 2) = hp;
          *(uint32_t*)(smem + O_SLO + row * 240 + col * 2) = lp;
        }
      }
    }
    __syncthreads();
  }

  // final: W = S*Xn ; P = 0.5(X + f*W) + eps*I
  for (int idx = tid; idx < NSD * NSD; idx += NS_THREADS) {
    int r = idx / NSD, c = idx - (idx / NSD) * NSD;
    float v = 0.f;
    if (r < NA && c < NA)
      v = ((r == c) ? (1.0f - 1e-4f) : Rg[r * NA + c]) * invf;
    __nv_bfloat16 h = __float2bfloat16(v);
    __nv_bfloat16 l = __float2bfloat16(v - __bfloat162float(h));
    uint32_t off = (uint32_t)(r * 240 + c * 2);
    *(__nv_bfloat16*)(smem + O_YHI + off) = h;
    *(__nv_bfloat16*)(smem + O_YLO + off) = l;
  }
  __syncthreads();
  gemm_ab(sb, O_SHI, O_SLO, O_YHI, O_YLO, wm, wn, lane, acc);
  __syncthreads();
#pragma unroll
  for (int nt = 0; nt < 7; nt++) {
#pragma unroll
    for (int half = 0; half < 2; half++) {
      int row = wm * 16 + (lane >> 2) + half * 8;
      int col = wn * 56 + nt * 8 + 2 * (lane & 3);
#pragma unroll
      for (int j = 0; j < 2; j++) {
        int c = col + j;
        float Xg = 0.f;
        if (row < NA && c < NA)
          Xg = (row == c) ? (1.0f - 1e-4f) : Rg[row * NA + c];
        float P = 0.5f * (Xg + fnorm * acc[nt][half * 2 + j]) +
                  ((row == c) ? 1e-4f : 0.f);
        S32[row * NSD + c] = P;
      }
    }
  }
  __syncthreads();

  if (tid < NA) aux[16 + tid] = rsqrtf(fmaxf(S32[tid * (NSD + 1)], 1e-6f));
  __syncthreads();

  const float* vl = g_vols + b * NA;
  float* og = out + (size_t)b * NA * NA;
  for (int idx = tid; idx < NA * NA; idx += NS_THREADS) {
    int r = idx / NA, c = idx - (idx / NA) * NA;
    og[idx] = vl[r] * vl[c] * aux[16 + r] * aux[16 + c] * S32[r * NSD + c];
  }
}

// ---------------------------------------------------------------------------
extern "C" void kernel_launch(void* const* d_in, const int* in_sizes, int n_in,
                              void* d_out, int out_size) {
  const float* x   = (const float*)d_in[0];
  const float* vw1 = (const float*)d_in[1];
  const float* vb1 = (const float*)d_in[2];
  const float* vw2 = (const float*)d_in[3];
  const float* vb2 = (const float*)d_in[4];
  const float* cw1 = (const float*)d_in[5];
  const float* cb1 = (const float*)d_in[6];
  const float* cw2 = (const float*)d_in[7];
  const float* cb2 = (const float*)d_in[8];
  float* out = (float*)d_out;

  prep_w1t<<<HID, DM>>>(cw1);

  cudaFuncSetAttribute(pair_mma_kernel,
                       cudaFuncAttributeMaxDynamicSharedMemorySize, SMEM_PAIR);
  pair_mma_kernel<<<dim3(PTILES + VTILES, BATCH), 256, SMEM_PAIR>>>(
      x, vw1, vb1, vw2, vb2, cb1, cw2, cb2);

  cudaFuncSetAttribute(psd_kernel,
                       cudaFuncAttributeMaxDynamicSharedMemorySize, SMEM_NS);
  psd_kernel<<<BATCH, NS_THREADS, SMEM_NS>>>(out);
}

// round 16
// speedup vs baseline: 1.0818x; 1.0296x over previous
#include <cuda_runtime.h>
#include <cuda_bf16.h>
#include <math.h>
#include <stdint.h>

#define NA 100
#define DM 256
#define HID 256
#define BATCH 64
#define NPAIR 4950
#define PT 64           // pairs per CTA tile
#define PTILES 78       // ceil(4950/64)
#define VTILES 7        // vols row-groups of 16

// ---------------- device scratch (no allocation allowed) ----------------
__device__ float g_R[BATCH * NA * NA];
__device__ float g_vols[BATCH * NA];
__device__ __nv_bfloat16 g_w1t_hi[HID * DM];  // [n][k] K-major
__device__ __nv_bfloat16 g_w1t_lo[HID * DM];

__device__ __forceinline__ uint32_t smem_u32(const void* p) {
  uint32_t a;
  asm("{ .reg .u64 t; cvta.to.shared.u64 t, %1; cvt.u32.u64 %0, t; }"
      : "=r"(a) : "l"(p));
  return a;
}
__device__ __forceinline__ void ldsm_x4(uint32_t (&r)[4], uint32_t addr) {
  asm volatile(
      "ldmatrix.sync.aligned.m8n8.x4.shared.b16 {%0,%1,%2,%3}, [%4];"
      : "=r"(r[0]), "=r"(r[1]), "=r"(r[2]), "=r"(r[3]) : "r"(addr));
}
__device__ __forceinline__ void ldsm_x2(uint32_t (&r)[2], uint32_t addr) {
  asm volatile(
      "ldmatrix.sync.aligned.m8n8.x2.shared.b16 {%0,%1}, [%2];"
      : "=r"(r[0]), "=r"(r[1]) : "r"(addr));
}
__device__ __forceinline__ void mma16816(float (&d)[4], const uint32_t (&a)[4],
                                         const uint32_t (&b)[2]) {
  asm volatile(
      "mma.sync.aligned.m16n8k16.row.col.f32.bf16.bf16.f32 "
      "{%0,%1,%2,%3}, {%4,%5,%6,%7}, {%8,%9}, {%0,%1,%2,%3};"
      : "+f"(d[0]), "+f"(d[1]), "+f"(d[2]), "+f"(d[3])
      : "r"(a[0]), "r"(a[1]), "r"(a[2]), "r"(a[3]), "r"(b[0]), "r"(b[1]));
}
__device__ __forceinline__ uint32_t pack_bf16(float a, float b) {
  __nv_bfloat16 h0 = __float2bfloat16(a), h1 = __float2bfloat16(b);
  return ((uint32_t)*(uint16_t*)&h1 << 16) | *(uint16_t*)&h0;
}
__device__ __forceinline__ void cp_async16(uint32_t dst, const void* src) {
  asm volatile("cp.async.ca.shared.global [%0], [%1], 16;"
               :: "r"(dst), "l"(src) : "memory");
}
#define CP_COMMIT() asm volatile("cp.async.commit_group;" ::: "memory")
#define CP_WAIT0()  asm volatile("cp.async.wait_group 0;" ::: "memory")

// ---------------------------------------------------------------------------
__global__ void prep_w1t(const float* __restrict__ w1) {
  int n = blockIdx.x, k = threadIdx.x;
  float v = w1[k * HID + n];
  __nv_bfloat16 h = __float2bfloat16(v);
  float r = v - __bfloat162float(h);
  g_w1t_hi[n * DM + k] = h;
  g_w1t_lo[n * DM + k] = __float2bfloat16(r);
}

// ---------------------------------------------------------------------------
// FUSED pair MLP (tiles 0..77) + vols MLP (tiles 78..84), per batch.
// pair: mma.sync bf16 2-way split, 3 passes, double-buffered, B via cp.async,
// A float4 staging, B fragments loaded pairwise via ldsm_x4.
// ---------------------------------------------------------------------------
#define SBUF 51200     // bytes per stage
#define SO_A_HI 0
#define SO_A_LO 5120
#define SO_B_HI 10240
#define SO_B_LO 30720
#define OFF_SI  102400
#define OFF_SJ  102656
#define OFF_B1  102912
#define OFF_W2  103936
#define OFF_RED 104960
#define SMEM_PAIR 105984

__global__ __launch_bounds__(256, 2) void pair_mma_kernel(
    const float* __restrict__ x,
    const float* __restrict__ vw1, const float* __restrict__ vb1,
    const float* __restrict__ vw2, const float* __restrict__ vb2,
    const float* __restrict__ b1, const float* __restrict__ w2,
    const float* __restrict__ b2) {
  extern __shared__ char smem[];
  uint32_t sb = smem_u32(smem);
  int b = blockIdx.y, tile = blockIdx.x;
  int tid = threadIdx.x, lane = tid & 31, warp = tid >> 5;
  const float* emb = x + ((size_t)b * 64 + 63) * NA * DM;

  if (tile >= PTILES) {
    // ================= vols branch =================
    int r0 = (tile - PTILES) * 16;
    float* es = (float*)smem;                  // [16][256]
    float* red = (float*)(smem + 16 * DM * 4); // [16][8]

    for (int idx = tid; idx < 16 * DM; idx += 256) {
      int r = idx >> 8, d = idx & 255;
      es[r * DM + d] = (r0 + r < NA) ? emb[(r0 + r) * DM + d] : 0.f;
    }
    __syncthreads();

    float acc[16];
    float bb = vb1[tid];
#pragma unroll
    for (int r = 0; r < 16; r++) acc[r] = bb;

#pragma unroll 4
    for (int d = 0; d < DM; d++) {
      float w = vw1[d * HID + tid];
#pragma unroll
      for (int r = 0; r < 16; r++) acc[r] = fmaf(es[r * DM + d], w, acc[r]);
    }

    float wv = vw2[tid];
#pragma unroll
    for (int r = 0; r < 16; r++) {
      float v = fmaxf(acc[r], 0.f) * wv;
#pragma unroll
      for (int o = 16; o; o >>= 1) v += __shfl_xor_sync(0xffffffffu, v, o);
      if (lane == 0) red[r * 8 + warp] = v;
    }
    __syncthreads();
    if (tid < 16) {
      float s = 0.f;
#pragma unroll
      for (int w = 0; w < 8; w++) s += red[tid * 8 + w];
      s += vb2[0];
      float sp = fmaxf(s, 0.f) + log1pf(expf(-fabsf(s)));
      if (r0 + tid < NA) g_vols[b * NA + r0 + tid] = sp + 1e-6f;
    }
    return;
  }

  // ================= pair branch =================
  int wm = warp >> 2, wn = warp & 3;   // 2 x 4 warps

  int* si = (int*)(smem + OFF_SI);
  int* sj = (int*)(smem + OFF_SJ);
  float* b1s = (float*)(smem + OFF_B1);
  float* w2s = (float*)(smem + OFF_W2);
  float* red = (float*)(smem + OFF_RED);

  if (tid < PT) {
    int k = tile * PT + tid;
    if (k >= NPAIR) k = NPAIR - 1;
    int i = (int)((1.0f + sqrtf(1.0f + 8.0f * (float)k)) * 0.5f);
    while ((i * (i - 1)) / 2 > k) i--;
    while (((i + 1) * i) / 2 <= k) i++;
    si[tid] = i;
    sj[tid] = k - (i * (i - 1)) / 2;
  }
  b1s[tid] = b1[tid];
  w2s[tid] = w2[tid];
  __syncthreads();

  float acc[2][8][4];
#pragma unroll
  for (int mt = 0; mt < 2; mt++)
#pragma unroll
    for (int nt = 0; nt < 8; nt++)
#pragma unroll
      for (int e = 0; e < 4; e++) acc[mt][nt][e] = 0.f;

#define STAGE_CHUNK(ch_, sbase_)                                              \
  do {                                                                        \
    int k0_ = (ch_) * 32;                                                     \
    _Pragma("unroll")                                                         \
    for (int t = 0; t < 4; t++) {                                             \
      int idx = tid + t * 256;                                                \
      int n = idx >> 2, kg = idx & 3;                                         \
      cp_async16(sb + (sbase_) + SO_B_HI + n * 80 + kg * 16,                  \
                 g_w1t_hi + n * DM + k0_ + kg * 8);                           \
      cp_async16(sb + (sbase_) + SO_B_LO + n * 80 + kg * 16,                  \
                 g_w1t_lo + n * DM + k0_ + kg * 8);                           \
    }                                                                         \
    CP_COMMIT();                                                              \
    _Pragma("unroll")                                                         \
    for (int t = 0; t < 2; t++) {                                             \
      int idx = tid + t * 256;                                                \
      int row = idx >> 3, kk4 = idx & 7;                                      \
      const float4 ea = *(const float4*)(emb + si[row] * DM + k0_ + 4 * kk4); \
      const float4 eb = *(const float4*)(emb + sj[row] * DM + k0_ + 4 * kk4); \
      float p0 = ea.x * eb.x, p1 = ea.y * eb.y;                               \
      float p2 = ea.z * eb.z, p3 = ea.w * eb.w;                               \
      __nv_bfloat16 h0 = __float2bfloat16(p0);                                \
      __nv_bfloat16 h1 = __float2bfloat16(p1);                                \
      __nv_bfloat16 h2 = __float2bfloat16(p2);                                \
      __nv_bfloat16 h3 = __float2bfloat16(p3);                                \
      uint32_t hp0 = ((uint32_t)*(uint16_t*)&h1 << 16) | *(uint16_t*)&h0;     \
      uint32_t hp1 = ((uint32_t)*(uint16_t*)&h3 << 16) | *(uint16_t*)&h2;     \
      uint32_t lp0 = pack_bf16(p0 - __bfloat162float(h0),                     \
                               p1 - __bfloat162float(h1));                    \
      uint32_t lp1 = pack_bf16(p2 - __bfloat162float(h2),                     \
                               p3 - __bfloat162float(h3));                    \
      *(uint2*)(smem + (sbase_) + SO_A_HI + row * 80 + kk4 * 8) =             \
          make_uint2(hp0, hp1);                                               \
      *(uint2*)(smem + (sbase_) + SO_A_LO + row * 80 + kk4 * 8) =             \
          make_uint2(lp0, lp1);                                               \
    }                                                                         \
  } while (0)

  // prologue: stage chunk 0 into buffer 0
  STAGE_CHUNK(0, 0);

  for (int ch = 0; ch < 8; ch++) {
    CP_WAIT0();
    __syncthreads();  // stage[ch] complete (and buffer ch^1 free)
    uint32_t cur = (uint32_t)((ch & 1) * SBUF);
    if (ch < 7) {
      uint32_t nxt = (uint32_t)(((ch + 1) & 1) * SBUF);
      STAGE_CHUNK(ch + 1, nxt);
    }
    // MMA phase on current buffer; B fragments loaded pairwise via ldsm_x4.
#pragma unroll
    for (int ks = 0; ks < 2; ks++) {
      uint32_t ah[2][4], al[2][4], bb[8][2];
      int arow = (lane & 7) + ((lane >> 3) & 1) * 8;
      int acolb = ks * 32 + ((lane >> 4) << 4);
#pragma unroll
      for (int mt = 0; mt < 2; mt++) {
        uint32_t ra = (uint32_t)((wm * 32 + mt * 16 + arow) * 80 + acolb);
        ldsm_x4(ah[mt], sb + cur + SO_A_HI + ra);
        ldsm_x4(al[mt], sb + cur + SO_A_LO + ra);
      }
      int brow_ = lane & 7;
      int bko = ks * 32 + (((lane >> 3) & 1) << 4);
      int bn2 = (lane >> 4) * 8;  // second tile of the pair for lanes 16-31
#pragma unroll
      for (int nt = 0; nt < 8; nt += 2) {
        uint32_t rb = (uint32_t)((wn * 64 + nt * 8 + bn2 + brow_) * 80 + bko);
        uint32_t t4[4];
        ldsm_x4(t4, sb + cur + SO_B_HI + rb);
        bb[nt][0] = t4[0]; bb[nt][1] = t4[1];
        bb[nt + 1][0] = t4[2]; bb[nt + 1][1] = t4[3];
      }
#pragma unroll
      for (int mt = 0; mt < 2; mt++)
#pragma unroll
        for (int nt = 0; nt < 8; nt++) mma16816(acc[mt][nt], ah[mt], bb[nt]);
#pragma unroll
      for (int mt = 0; mt < 2; mt++)
#pragma unroll
        for (int nt = 0; nt < 8; nt++) mma16816(acc[mt][nt], al[mt], bb[nt]);
#pragma unroll
      for (int nt = 0; nt < 8; nt += 2) {
        uint32_t rb = (uint32_t)((wn * 64 + nt * 8 + bn2 + brow_) * 80 + bko);
        uint32_t t4[4];
        ldsm_x4(t4, sb + cur + SO_B_LO + rb);
        bb[nt][0] = t4[0]; bb[nt][1] = t4[1];
        bb[nt + 1][0] = t4[2]; bb[nt + 1][1] = t4[3];
      }
#pragma unroll
      for (int mt = 0; mt < 2; mt++)
#pragma unroll
        for (int nt = 0; nt < 8; nt++) mma16816(acc[mt][nt], ah[mt], bb[nt]);
    }
  }

  // Epilogue: relu(h + b1) . w2, quad shuffle-reduce, cross-warp reduce
#pragma unroll
  for (int mt = 0; mt < 2; mt++) {
#pragma unroll
    for (int half = 0; half < 2; half++) {
      float s = 0.f;
#pragma unroll
      for (int nt = 0; nt < 8; nt++) {
        int col = wn * 64 + nt * 8 + 2 * (lane & 3);
        float h0 = acc[mt][nt][half * 2 + 0] + b1s[col];
        float h1 = acc[mt][nt][half * 2 + 1] + b1s[col + 1];
        s = fmaf(fmaxf(h0, 0.f), w2s[col], s);
        s = fmaf(fmaxf(h1, 0.f), w2s[col + 1], s);
      }
      s += __shfl_xor_sync(0xffffffffu, s, 1);
      s += __shfl_xor_sync(0xffffffffu, s, 2);
      if ((lane & 3) == 0) {
        int row = wm * 32 + mt * 16 + half * 8 + (lane >> 2);
        red[row * 4 + wn] = s;
      }
    }
  }
  __syncthreads();
  if (tid < PT) {
    int k = tile * PT + tid;
    if (k < NPAIR) {
      float s = red[tid * 4] + red[tid * 4 + 1] + red[tid * 4 + 2] +
                red[tid * 4 + 3] + b2[0];
      float t = tanhf(s);
      int i = si[tid], j = sj[tid];
      g_R[(size_t)b * NA * NA + i * NA + j] = t;
      g_R[(size_t)b * NA * NA + j * NA + i] = t;
    }
  }
}

// ---------------------------------------------------------------------------
// PSD projection via HYBRID matrix-sign iteration:
//   10 quintic iters (symmetrize each), 4 cubic iters (symmetrize odd only),
//   R_psd = 0.5(X + X*S) + eps*I.  112^3 bf16 hi/lo 3-pass GEMMs.
// ---------------------------------------------------------------------------
#define QI 10
#define CI 4
#define QA 3.4445f
#define QB (-4.7750f)
#define QC 2.0315f
#define NSD 112
#define NS_THREADS 448
#define NS_TRI (NSD * (NSD + 1) / 2)
#define NPK 15
#define O_S32 0
#define O_SHI 50176
#define O_SLO 77056
#define O_YHI 103936
#define O_YLO 130816
#define O_THI 157696
#define O_TLO 184576
#define O_AUX 211456
#define SMEM_NS (211456 + 512 + 64)

__device__ __forceinline__ void gemm_ab(uint32_t sb, uint32_t oAh, uint32_t oAl,
                                        uint32_t oBh, uint32_t oBl,
                                        int wm, int wn, int lane,
                                        float (&acc)[7][4]) {
#pragma unroll
  for (int nt = 0; nt < 7; nt++)
#pragma unroll
    for (int e = 0; e < 4; e++) acc[nt][e] = 0.f;
#pragma unroll
  for (int ks = 0; ks < 7; ks++) {
    uint32_t ah[4], al[4], bb[7][2];
    int arow = (lane & 7) + ((lane >> 3) & 1) * 8;
    uint32_t ra = (uint32_t)((wm * 16 + arow) * 240 + ks * 32 + ((lane >> 4) << 4));
    ldsm_x4(ah, sb + oAh + ra);
    ldsm_x4(al, sb + oAl + ra);
    int brow_ = lane & 7;
    int bko = ks * 32 + (((lane >> 3) & 1) << 4);
    int bn2 = (lane >> 4) * 8;
#pragma unroll
    for (int nt = 0; nt < 6; nt += 2) {
      uint32_t rb = (uint32_t)((wn * 56 + nt * 8 + bn2 + brow_) * 240 + bko);
      uint32_t t4[4];
      ldsm_x4(t4, sb + oBh + rb);
      bb[nt][0] = t4[0]; bb[nt][1] = t4[1];
      bb[nt + 1][0] = t4[2]; bb[nt + 1][1] = t4[3];
    }
    {
      uint32_t rb = (uint32_t)((wn * 56 + 6 * 8 + (lane & 7)) * 240 +
                               ks * 32 + (((lane >> 3) & 1) << 4));
      ldsm_x2(bb[6], sb + oBh + rb);
    }
#pragma unroll
    for (int nt = 0; nt < 7; nt++) mma16816(acc[nt], ah, bb[nt]);
#pragma unroll
    for (int nt = 0; nt < 7; nt++) mma16816(acc[nt], al, bb[nt]);
#pragma unroll
    for (int nt = 0; nt < 6; nt += 2) {
      uint32_t rb = (uint32_t)((wn * 56 + nt * 8 + bn2 + brow_) * 240 + bko);
      uint32_t t4[4];
      ldsm_x4(t4, sb + oBl + rb);
      bb[nt][0] = t4[0]; bb[nt][1] = t4[1];
      bb[nt + 1][0] = t4[2]; bb[nt + 1][1] = t4[3];
    }
    {
      uint32_t rb = (uint32_t)((wn * 56 + 6 * 8 + (lane & 7)) * 240 +
                               ks * 32 + (((lane >> 3) & 1) << 4));
      ldsm_x2(bb[6], sb + oBl + rb);
    }
#pragma unroll
    for (int nt = 0; nt < 7; nt++) mma16816(acc[nt], ah, bb[nt]);
  }
}

__global__ __launch_bounds__(NS_THREADS) void psd_kernel(float* __restrict__ out) {
  extern __shared__ char smem[];
  uint32_t sb = smem_u32(smem);
  float* S32 = (float*)(smem + O_S32);
  float* aux = (float*)(smem + O_AUX);
  int b = blockIdx.x;
  int tid = threadIdx.x, lane = tid & 31, warp = tid >> 5;
  int wm = warp % 7, wn = warp / 7;
  const float* Rg = g_R + (size_t)b * NA * NA;

  int psi[NPK], psj[NPK];
#pragma unroll
  for (int k = 0; k < NPK; k++) {
    int idx = tid + k * NS_THREADS;
    if (idx < NS_TRI) {
      int i = (int)((sqrtf(8.f * (float)idx + 1.f) - 1.f) * 0.5f);
      while (i * (i + 1) / 2 > idx) i--;
      while ((i + 1) * (i + 2) / 2 <= idx) i++;
      psi[k] = i;
      psj[k] = idx - i * (i + 1) / 2;
    } else {
      psi[k] = 0;
      psj[k] = 0;
    }
  }

#define SYMMETRIZE_REFRESH()                                                  \
  do {                                                                        \
    _Pragma("unroll")                                                         \
    for (int k = 0; k < NPK; k++) {                                           \
      if (tid + k * NS_THREADS < NS_TRI) {                                    \
        int i = psi[k], j = psj[k];                                           \
        float avg = 0.5f * (S32[i * NSD + j] + S32[j * NSD + i]);             \
        avg = fminf(fmaxf(avg, -2.f), 2.f);                                   \
        S32[i * NSD + j] = avg;                                               \
        S32[j * NSD + i] = avg;                                               \
        __nv_bfloat16 h = __float2bfloat16(avg);                              \
        __nv_bfloat16 l = __float2bfloat16(avg - __bfloat162float(h));        \
        uint32_t oij = (uint32_t)(i * 240 + j * 2);                           \
        uint32_t oji = (uint32_t)(j * 240 + i * 2);                           \
        *(__nv_bfloat16*)(smem + O_SHI + oij) = h;                            \
        *(__nv_bfloat16*)(smem + O_SLO + oij) = l;                            \
        *(__nv_bfloat16*)(smem + O_SHI + oji) = h;                            \
        *(__nv_bfloat16*)(smem + O_SLO + oji) = l;                            \
      }                                                                       \
    }                                                                         \
  } while (0)

  float part = 0.f;
  for (int idx = tid; idx < NSD * NSD; idx += NS_THREADS) {
    int r = idx / NSD, c = idx - (idx / NSD) * NSD;
    float v = 0.f;
    if (r < NA && c < NA) v = (r == c) ? (1.0f - 1e-4f) : Rg[r * NA + c];
    S32[idx] = v;
    part += v * v;
  }
#pragma unroll
  for (int o = 16; o; o >>= 1) part += __shfl_xor_sync(0xffffffffu, part, o);
  if (lane == 0) aux[warp] = part;
  __syncthreads();
  if (tid == 0) {
    float s = 0.f;
    for (int w = 0; w < 14; w++) s += aux[w];
    float f = sqrtf(s);
    aux[14] = f;
    aux[15] = 1.0f / f;
  }
  __syncthreads();
  float fnorm = aux[14], invf = aux[15];

  for (int idx = tid; idx < NSD * NSD; idx += NS_THREADS) {
    int r = idx / NSD, c = idx - (idx / NSD) * NSD;
    float v = S32[idx] * invf;
    S32[idx] = v;
    __nv_bfloat16 h = __float2bfloat16(v);
    __nv_bfloat16 l = __float2bfloat16(v - __bfloat162float(h));
    uint32_t off = (uint32_t)(r * 240 + c * 2);
    *(__nv_bfloat16*)(smem + O_SHI + off) = h;
    *(__nv_bfloat16*)(smem + O_SLO + off) = l;
  }
  __syncthreads();

  float acc[7][4];

  // Phase 1: quintic
  for (int it = 0; it < QI; it++) {
    gemm_ab(sb, O_SHI, O_SLO, O_SHI, O_SLO, wm, wn, lane, acc);
#pragma unroll
    for (int nt = 0; nt < 7; nt++) {
#pragma unroll
      for (int half = 0; half < 2; half++) {
        int row = wm * 16 + (lane >> 2) + half * 8;
        int col = wn * 56 + nt * 8 + 2 * (lane & 3);
        float a0 = acc[nt][half * 2 + 0], a1 = acc[nt][half * 2 + 1];
        __nv_bfloat16 h0 = __float2bfloat16(a0), h1 = __float2bfloat16(a1);
        float r0 = a0 - __bfloat162float(h0), r1 = a1 - __bfloat162float(h1);
        uint32_t hp = ((uint32_t)*(uint16_t*)&h1 << 16) | *(uint16_t*)&h0;
        uint32_t lp = pack_bf16(r0, r1);
        *(uint32_t*)(smem + O_YHI + row * 240 + col * 2) = hp;
        *(uint32_t*)(smem + O_YLO + row * 240 + col * 2) = lp;
      }
    }
    __syncthreads();
    gemm_ab(sb, O_YHI, O_YLO, O_YHI, O_YLO, wm, wn, lane, acc);
    __syncthreads();
#pragma unroll
    for (int nt = 0; nt < 7; nt++) {
#pragma unroll
      for (int half = 0; half < 2; half++) {
        int row = wm * 16 + (lane >> 2) + half * 8;
        int col = wn * 56 + nt * 8 + 2 * (lane & 3);
        float t01[2];
#pragma unroll
        for (int j = 0; j < 2; j++) {
          int c = col + j;
          uint32_t off = (uint32_t)(row * 240 + c * 2);
          float y = __bfloat162float(*(__nv_bfloat16*)(smem + O_YHI + off)) +
                    __bfloat162float(*(__nv_bfloat16*)(smem + O_YLO + off));
          t01[j] = ((row == c) ? QA : 0.f) + QB * y + QC * acc[nt][half * 2 + j];
        }
        __nv_bfloat16 h0 = __float2bfloat16(t01[0]), h1 = __float2bfloat16(t01[1]);
        float r0 = t01[0] - __bfloat162float(h0), r1 = t01[1] - __bfloat162float(h1);
        uint32_t hp = ((uint32_t)*(uint16_t*)&h1 << 16) | *(uint16_t*)&h0;
        uint32_t lp = pack_bf16(r0, r1);
        *(uint32_t*)(smem + O_THI + row * 240 + col * 2) = hp;
        *(uint32_t*)(smem + O_TLO + row * 240 + col * 2) = lp;
      }
    }
    __syncthreads();
    gemm_ab(sb, O_SHI, O_SLO, O_THI, O_TLO, wm, wn, lane, acc);
    __syncthreads();
#pragma unroll
    for (int nt = 0; nt < 7; nt++) {
#pragma unroll
      for (int half = 0; half < 2; half++) {
        int row = wm * 16 + (lane >> 2) + half * 8;
        int col = wn * 56 + nt * 8 + 2 * (lane & 3);
        int i0 = row * NSD + col;
        S32[i0]     = acc[nt][half * 2 + 0];
        S32[i0 + 1] = acc[nt][half * 2 + 1];
      }
    }
    __syncthreads();
    SYMMETRIZE_REFRESH();
    __syncthreads();
  }

  // Phase 2: cubic polish (symmetrize on odd iters only)
  for (int it = 0; it < CI; it++) {
    gemm_ab(sb, O_SHI, O_SLO, O_SHI, O_SLO, wm, wn, lane, acc);
#pragma unroll
    for (int nt = 0; nt < 7; nt++) {
#pragma unroll
      for (int half = 0; half < 2; half++) {
        int row = wm * 16 + (lane >> 2) + half * 8;
        int col = wn * 56 + nt * 8 + 2 * (lane & 3);
        float a0 = acc[nt][half * 2 + 0], a1 = acc[nt][half * 2 + 1];
        __nv_bfloat16 h0 = __float2bfloat16(a0), h1 = __float2bfloat16(a1);
        float r0 = a0 - __bfloat162float(h0), r1 = a1 - __bfloat162float(h1);
        uint32_t hp = ((uint32_t)*(uint16_t*)&h1 << 16) | *(uint16_t*)&h0;
        uint32_t lp = pack_bf16(r0, r1);
        *(uint32_t*)(smem + O_YHI + row * 240 + col * 2) = hp;
        *(uint32_t*)(smem + O_YLO + row * 240 + col * 2) = lp;
      }
    }
    __syncthreads();
    gemm_ab(sb, O_SHI, O_SLO, O_YHI, O_YLO, wm, wn, lane, acc);
    __syncthreads();
    if (it & 1) {
#pragma unroll
      for (int nt = 0; nt < 7; nt++) {
#pragma unroll
        for (int half = 0; half < 2; half++) {
          int row = wm * 16 + (lane >> 2) + half * 8;
          int col = wn * 56 + nt * 8 + 2 * (lane & 3);
          int i0 = row * NSD + col;
          S32[i0]     = 1.5f * S32[i0]     - 0.5f * acc[nt][half * 2 + 0];
          S32[i0 + 1] = 1.5f * S32[i0 + 1] - 0.5f * acc[nt][half * 2 + 1];
        }
      }
      __syncthreads();
      SYMMETRIZE_REFRESH();
    } else {
#pragma unroll
      for (int nt = 0; nt < 7; nt++) {
#pragma unroll
        for (int half = 0; half < 2; half++) {
          int row = wm * 16 + (lane >> 2) + half * 8;
          int col = wn * 56 + nt * 8 + 2 * (lane & 3);
          int i0 = row * NSD + col;
          float s0 = 1.5f * S32[i0]     - 0.5f * acc[nt][half * 2 + 0];
          float s1 = 1.5f * S32[i0 + 1] - 0.5f * acc[nt][half * 2 + 1];
          S32[i0] = s0;
          S32[i0 + 1] = s1;
          __nv_bfloat16 h0 = __float2bfloat16(s0), h1 = __float2bfloat16(s1);
          float r0 = s0 - __bfloat162float(h0), r1 = s1 - __bfloat162float(h1);
          uint32_t hp = ((uint32_t)*(uint16_t*)&h1 << 16) | *(uint16_t*)&h0;
          uint32_t lp = pack_bf16(r0, r1);
          *(uint32_t*)(smem + O_SHI + row * 240 + col * 2) = hp;
          *(uint32_t*)(smem + O_SLO + row * 240 + col * 2) = lp;
        }
      }
    }
    __syncthreads();
  }

  // final: W = S*Xn ; P = 0.5(X + f*W) + eps*I
  for (int idx = tid; idx < NSD * NSD; idx += NS_THREADS) {
    int r = idx / NSD, c = idx - (idx / NSD) * NSD;
    float v = 0.f;
    if (r < NA && c < NA)
      v = ((r == c) ? (1.0f - 1e-4f) : Rg[r * NA + c]) * invf;
    __nv_bfloat16 h = __float2bfloat16(v);
    __nv_bfloat16 l = __float2bfloat16(v - __bfloat162float(h));
    uint32_t off = (uint32_t)(r * 240 + c * 2);
    *(__nv_bfloat16*)(smem + O_YHI + off) = h;
    *(__nv_bfloat16*)(smem + O_YLO + off) = l;
  }
  __syncthreads();
  gemm_ab(sb, O_SHI, O_SLO, O_YHI, O_YLO, wm, wn, lane, acc);
  __syncthreads();
#pragma unroll
  for (int nt = 0; nt < 7; nt++) {
#pragma unroll
    for (int half = 0; half < 2; half++) {
      int row = wm * 16 + (lane >> 2) + half * 8;
      int col = wn * 56 + nt * 8 + 2 * (lane & 3);
#pragma unroll
      for (int j = 0; j < 2; j++) {
        int c = col + j;
        float Xg = 0.f;
        if (row < NA && c < NA)
          Xg = (row == c) ? (1.0f - 1e-4f) : Rg[row * NA + c];
        float P = 0.5f * (Xg + fnorm * acc[nt][half * 2 + j]) +
                  ((row == c) ? 1e-4f : 0.f);
        S32[row * NSD + c] = P;
      }
    }
  }
  __syncthreads();

  if (tid < NA) aux[16 + tid] = rsqrtf(fmaxf(S32[tid * (NSD + 1)], 1e-6f));
  __syncthreads();

  const float* vl = g_vols + b * NA;
  float* og = out + (size_t)b * NA * NA;
  for (int idx = tid; idx < NA * NA; idx += NS_THREADS) {
    int r = idx / NA, c = idx - (idx / NA) * NA;
    og[idx] = vl[r] * vl[c] * aux[16 + r] * aux[16 + c] * S32[r * NSD + c];
  }
}

// ---------------------------------------------------------------------------
extern "C" void kernel_launch(void* const* d_in, const int* in_sizes, int n_in,
                              void* d_out, int out_size) {
  const float* x   = (const float*)d_in[0];
  const float* vw1 = (const float*)d_in[1];
  const float* vb1 = (const float*)d_in[2];
  const float* vw2 = (const float*)d_in[3];
  const float* vb2 = (const float*)d_in[4];
  const float* cw1 = (const float*)d_in[5];
  const float* cb1 = (const float*)d_in[6];
  const float* cw2 = (const float*)d_in[7];
  const float* cb2 = (const float*)d_in[8];
  float* out = (float*)d_out;

  prep_w1t<<<HID, DM>>>(cw1);

  cudaFuncSetAttribute(pair_mma_kernel,
                       cudaFuncAttributeMaxDynamicSharedMemorySize, SMEM_PAIR);
  pair_mma_kernel<<<dim3(PTILES + VTILES, BATCH), 256, SMEM_PAIR>>>(
      x, vw1, vb1, vw2, vb2, cb1, cw2, cb2);

  cudaFuncSetAttribute(psd_kernel,
                       cudaFuncAttributeMaxDynamicSharedMemorySize, SMEM_NS);
  psd_kernel<<<BATCH, NS_THREADS, SMEM_NS>>>(out);
}